// round 2
// baseline (speedup 1.0000x reference)
#include <cuda_runtime.h>
#include <math.h>

#define L_DIM 2048
#define S_DIM 2048
#define N_B   4
#define E_DIM 256
#define H_N   8
#define HD_N  32
#define NH_N  32
#define SCALING 0.17677669529663687f   // 32^-0.5

// Scratch (allocation-free rule: __device__ globals)
__device__ float g_q[(size_t)NH_N * L_DIM * HD_N];      // (NH, L, HD), pre-scaled + bias
__device__ float g_k[(size_t)NH_N * S_DIM * HD_N];      // (NH, S, HD)
__device__ float g_v[(size_t)NH_N * S_DIM * HD_N];      // (NH, S, HD)
__device__ float g_attn[(size_t)L_DIM * N_B * E_DIM];   // (L*N, E)

// ---------------------------------------------------------------------------
// QKV projection: C[m][e] = sum_k A[m][k] * W[z*E+e][k] + bias[z*E+e], scaled
// for z==0 (query). Output scattered to (NH, L, HD) layout.
// Grid: (M/64=128, E/64=4, 3), 256 threads, 64x64 tile, 4x4 microtile.
// ---------------------------------------------------------------------------
__global__ __launch_bounds__(256)
void qkv_proj_kernel(const float* __restrict__ q_in,
                     const float* __restrict__ k_in,
                     const float* __restrict__ v_in,
                     const float* __restrict__ W,
                     const float* __restrict__ bias)
{
    __shared__ float sA[16][68];   // [k][m], pad 68 (16B-aligned float4 rows)
    __shared__ float sB[16][68];   // [k][n]

    const int z = blockIdx.z;
    const float* A  = (z == 0) ? q_in : (z == 1) ? k_in : v_in;
    const float* Wz = W + (size_t)z * E_DIM * E_DIM;
    const float* bz = bias + z * E_DIM;
    float* Cz = (z == 0) ? g_q : (z == 1) ? g_k : g_v;
    const float scale = (z == 0) ? SCALING : 1.0f;

    const int tid = threadIdx.x;
    const int m0 = blockIdx.x * 64;
    const int n0 = blockIdx.y * 64;
    const int lr = tid >> 2;           // 0..63 (load row)
    const int lc = (tid & 3) << 2;     // 0,4,8,12 (load col base)
    const int ty = tid >> 4;           // 0..15 row group
    const int tx = tid & 15;           // 0..15 col group

    float acc[4][4];
#pragma unroll
    for (int i = 0; i < 4; i++)
#pragma unroll
        for (int j = 0; j < 4; j++) acc[i][j] = 0.f;

    for (int kb = 0; kb < E_DIM; kb += 16) {
        float4 av = *(const float4*)(A  + (size_t)(m0 + lr) * E_DIM + kb + lc);
        float4 bv = *(const float4*)(Wz + (size_t)(n0 + lr) * E_DIM + kb + lc);
        __syncthreads();
        sA[lc + 0][lr] = av.x; sA[lc + 1][lr] = av.y;
        sA[lc + 2][lr] = av.z; sA[lc + 3][lr] = av.w;
        sB[lc + 0][lr] = bv.x; sB[lc + 1][lr] = bv.y;
        sB[lc + 2][lr] = bv.z; sB[lc + 3][lr] = bv.w;
        __syncthreads();
#pragma unroll
        for (int kk = 0; kk < 16; kk++) {
            float4 a = *(const float4*)&sA[kk][ty << 2];
            float4 b = *(const float4*)&sB[kk][tx << 2];
            acc[0][0] += a.x * b.x; acc[0][1] += a.x * b.y; acc[0][2] += a.x * b.z; acc[0][3] += a.x * b.w;
            acc[1][0] += a.y * b.x; acc[1][1] += a.y * b.y; acc[1][2] += a.y * b.z; acc[1][3] += a.y * b.w;
            acc[2][0] += a.z * b.x; acc[2][1] += a.z * b.y; acc[2][2] += a.z * b.z; acc[2][3] += a.z * b.w;
            acc[3][0] += a.w * b.x; acc[3][1] += a.w * b.y; acc[3][2] += a.w * b.z; acc[3][3] += a.w * b.w;
        }
    }

    const int e0 = n0 + (tx << 2);
    float4 b4 = *(const float4*)(bz + e0);
    const int h = e0 >> 5, d = e0 & 31;     // 4 cols stay inside one head (32|4)
#pragma unroll
    for (int i = 0; i < 4; i++) {
        const int m = m0 + (ty << 2) + i;
        const int l = m >> 2, n = m & 3;    // m = l*N + n
        const int bh = n * H_N + h;
        float4 o;
        o.x = (acc[i][0] + b4.x) * scale;
        o.y = (acc[i][1] + b4.y) * scale;
        o.z = (acc[i][2] + b4.z) * scale;
        o.w = (acc[i][3] + b4.w) * scale;
        *(float4*)(Cz + ((size_t)bh * L_DIM + l) * HD_N + d) = o;
    }
}

// ---------------------------------------------------------------------------
// Attention: per CTA one (bh, 64-row L tile). Stream S in 64-col chunks.
// rel matrix streamed straight from gmem (zero reuse). Online softmax.
// Grid: (L/64=32, NH=32), 256 threads.
// Thread map: rg=tid>>4 owns 4 rows; cg=tid&15 owns 4 score cols and
// 2 output dims. Row reductions: 16-lane (half-warp) shfl.
// Loads: each thread covers row lr at cols {lc, lc+16} -> full 32 dims.
// ---------------------------------------------------------------------------
__global__ __launch_bounds__(256)
void attn_kernel(const float* __restrict__ rel)
{
    __shared__ float sQT[32][68];   // [d][row]
    __shared__ float sKT[32][68];   // [d][col]
    __shared__ float sV[64][36];    // [s][d]
    __shared__ float sP[64][68];    // [row][s]

    const int bh = blockIdx.y;
    const int l0 = blockIdx.x * 64;
    const int tid = threadIdx.x;
    const int rg = tid >> 4;
    const int cg = tid & 15;
    const int lr = tid >> 2;          // 0..63
    const int lc = (tid & 3) << 2;    // 0,4,8,12

    // Load Q tile transposed: sQT[d][r], both 16-col halves
    {
        const float* qrow = g_q + ((size_t)bh * L_DIM + l0 + lr) * HD_N;
        float4 q0 = *(const float4*)(qrow + lc);
        float4 q1 = *(const float4*)(qrow + lc + 16);
        sQT[lc + 0][lr] = q0.x; sQT[lc + 1][lr] = q0.y;
        sQT[lc + 2][lr] = q0.z; sQT[lc + 3][lr] = q0.w;
        sQT[lc + 16][lr] = q1.x; sQT[lc + 17][lr] = q1.y;
        sQT[lc + 18][lr] = q1.z; sQT[lc + 19][lr] = q1.w;
    }

    float O[4][2];
    float mrow[4], lrow[4];
#pragma unroll
    for (int i = 0; i < 4; i++) {
        O[i][0] = 0.f; O[i][1] = 0.f;
        mrow[i] = -INFINITY; lrow[i] = 0.f;
    }

    const float* relBase = rel + ((size_t)bh * L_DIM + (l0 + (rg << 2))) * S_DIM + (cg << 2);

    for (int s0 = 0; s0 < S_DIM; s0 += 64) {
        __syncthreads();   // prev-iter AV reads of sV/sP done before overwrite
        {
            const float* krow = g_k + ((size_t)bh * S_DIM + s0 + lr) * HD_N;
            float4 k0 = *(const float4*)(krow + lc);
            float4 k1 = *(const float4*)(krow + lc + 16);
            sKT[lc + 0][lr] = k0.x; sKT[lc + 1][lr] = k0.y;
            sKT[lc + 2][lr] = k0.z; sKT[lc + 3][lr] = k0.w;
            sKT[lc + 16][lr] = k1.x; sKT[lc + 17][lr] = k1.y;
            sKT[lc + 18][lr] = k1.z; sKT[lc + 19][lr] = k1.w;
            const float* vrow = g_v + ((size_t)bh * S_DIM + s0 + lr) * HD_N;
            *(float4*)&sV[lr][lc]      = *(const float4*)(vrow + lc);
            *(float4*)&sV[lr][lc + 16] = *(const float4*)(vrow + lc + 16);
        }
        __syncthreads();

        // ---- scores: acc = rel + q·k (q pre-scaled) ----
        float acc[4][4];
#pragma unroll
        for (int i = 0; i < 4; i++) {
            float4 rv = *(const float4*)(relBase + (size_t)i * S_DIM + s0);
            acc[i][0] = rv.x; acc[i][1] = rv.y; acc[i][2] = rv.z; acc[i][3] = rv.w;
        }
#pragma unroll
        for (int k = 0; k < 32; k++) {
            float4 a = *(const float4*)&sQT[k][rg << 2];
            float4 b = *(const float4*)&sKT[k][cg << 2];
            acc[0][0] += a.x * b.x; acc[0][1] += a.x * b.y; acc[0][2] += a.x * b.z; acc[0][3] += a.x * b.w;
            acc[1][0] += a.y * b.x; acc[1][1] += a.y * b.y; acc[1][2] += a.y * b.z; acc[1][3] += a.y * b.w;
            acc[2][0] += a.z * b.x; acc[2][1] += a.z * b.y; acc[2][2] += a.z * b.z; acc[2][3] += a.z * b.w;
            acc[3][0] += a.w * b.x; acc[3][1] += a.w * b.y; acc[3][2] += a.w * b.z; acc[3][3] += a.w * b.w;
        }

        // ---- online softmax (per row, reduce over 16 lanes of a half-warp) ----
#pragma unroll
        for (int i = 0; i < 4; i++) {
            float mx = fmaxf(fmaxf(acc[i][0], acc[i][1]), fmaxf(acc[i][2], acc[i][3]));
#pragma unroll
            for (int o = 8; o > 0; o >>= 1)
                mx = fmaxf(mx, __shfl_xor_sync(0xffffffffu, mx, o));
            const float mnew = fmaxf(mrow[i], mx);
            float p0 = __expf(acc[i][0] - mnew);
            float p1 = __expf(acc[i][1] - mnew);
            float p2 = __expf(acc[i][2] - mnew);
            float p3 = __expf(acc[i][3] - mnew);
            float sum = (p0 + p1) + (p2 + p3);
#pragma unroll
            for (int o = 8; o > 0; o >>= 1)
                sum += __shfl_xor_sync(0xffffffffu, sum, o);
            const float fac = __expf(mrow[i] - mnew);
            lrow[i] = lrow[i] * fac + sum;
            mrow[i] = mnew;
            O[i][0] *= fac; O[i][1] *= fac;
            *(float4*)&sP[(rg << 2) + i][cg << 2] = make_float4(p0, p1, p2, p3);
        }
        __syncthreads();

        // ---- AV: O[i][jd] += sum_s P[r][s] * V[s][d0+jd] ----
        const int d0 = cg << 1;
#pragma unroll
        for (int s = 0; s < 64; s += 4) {
            float2 v0 = *(const float2*)&sV[s + 0][d0];
            float2 v1 = *(const float2*)&sV[s + 1][d0];
            float2 v2 = *(const float2*)&sV[s + 2][d0];
            float2 v3 = *(const float2*)&sV[s + 3][d0];
#pragma unroll
            for (int i = 0; i < 4; i++) {
                float4 p = *(const float4*)&sP[(rg << 2) + i][s];
                O[i][0] += p.x * v0.x + p.y * v1.x + p.z * v2.x + p.w * v3.x;
                O[i][1] += p.x * v0.y + p.y * v1.y + p.z * v2.y + p.w * v3.y;
            }
        }
    }

    // ---- epilogue: normalize, write (L*N, E) layout ----
    const int n = bh >> 3, h = bh & 7;
#pragma unroll
    for (int i = 0; i < 4; i++) {
        const int l = l0 + (rg << 2) + i;
        const float inv = 1.0f / lrow[i];
        float2 o2 = make_float2(O[i][0] * inv, O[i][1] * inv);
        *(float2*)(g_attn + ((size_t)l * N_B + n) * E_DIM + h * HD_N + (cg << 1)) = o2;
    }
}

// ---------------------------------------------------------------------------
// Output projection: out[m][e] = sum_k attn[m][k] * Wo[e][k] + bo[e]
// Grid: (128, 4), 256 threads.
// ---------------------------------------------------------------------------
__global__ __launch_bounds__(256)
void out_proj_kernel(const float* __restrict__ W,
                     const float* __restrict__ bias,
                     float* __restrict__ out)
{
    __shared__ float sA[16][68];
    __shared__ float sB[16][68];

    const int tid = threadIdx.x;
    const int m0 = blockIdx.x * 64;
    const int n0 = blockIdx.y * 64;
    const int lr = tid >> 2;
    const int lc = (tid & 3) << 2;
    const int ty = tid >> 4;
    const int tx = tid & 15;

    float acc[4][4];
#pragma unroll
    for (int i = 0; i < 4; i++)
#pragma unroll
        for (int j = 0; j < 4; j++) acc[i][j] = 0.f;

    for (int kb = 0; kb < E_DIM; kb += 16) {
        float4 av = *(const float4*)(g_attn + (size_t)(m0 + lr) * E_DIM + kb + lc);
        float4 bv = *(const float4*)(W      + (size_t)(n0 + lr) * E_DIM + kb + lc);
        __syncthreads();
        sA[lc + 0][lr] = av.x; sA[lc + 1][lr] = av.y;
        sA[lc + 2][lr] = av.z; sA[lc + 3][lr] = av.w;
        sB[lc + 0][lr] = bv.x; sB[lc + 1][lr] = bv.y;
        sB[lc + 2][lr] = bv.z; sB[lc + 3][lr] = bv.w;
        __syncthreads();
#pragma unroll
        for (int kk = 0; kk < 16; kk++) {
            float4 a = *(const float4*)&sA[kk][ty << 2];
            float4 b = *(const float4*)&sB[kk][tx << 2];
            acc[0][0] += a.x * b.x; acc[0][1] += a.x * b.y; acc[0][2] += a.x * b.z; acc[0][3] += a.x * b.w;
            acc[1][0] += a.y * b.x; acc[1][1] += a.y * b.y; acc[1][2] += a.y * b.z; acc[1][3] += a.y * b.w;
            acc[2][0] += a.z * b.x; acc[2][1] += a.z * b.y; acc[2][2] += a.z * b.z; acc[2][3] += a.z * b.w;
            acc[3][0] += a.w * b.x; acc[3][1] += a.w * b.y; acc[3][2] += a.w * b.z; acc[3][3] += a.w * b.w;
        }
    }

    const int e0 = n0 + (tx << 2);
    float4 b4 = *(const float4*)(bias + e0);
#pragma unroll
    for (int i = 0; i < 4; i++) {
        const int m = m0 + (ty << 2) + i;
        float4 o;
        o.x = acc[i][0] + b4.x;
        o.y = acc[i][1] + b4.y;
        o.z = acc[i][2] + b4.z;
        o.w = acc[i][3] + b4.w;
        *(float4*)(out + (size_t)m * E_DIM + e0) = o;
    }
}

// ---------------------------------------------------------------------------
extern "C" void kernel_launch(void* const* d_in, const int* in_sizes, int n_in,
                              void* d_out, int out_size)
{
    const float* query = (const float*)d_in[0];
    const float* key   = (const float*)d_in[1];
    const float* value = (const float*)d_in[2];
    const float* rel   = (const float*)d_in[3];
    const float* ipw   = (const float*)d_in[4];
    const float* ipb   = (const float*)d_in[5];
    const float* opw   = (const float*)d_in[6];
    const float* opb   = (const float*)d_in[7];
    float* out = (float*)d_out;

    dim3 g1(128, 4, 3);
    qkv_proj_kernel<<<g1, 256>>>(query, key, value, ipw, ipb);

    dim3 g2(32, 32);   // x = L tiles (fast) so same-bh CTAs share K/V in L2
    attn_kernel<<<g2, 256>>>(rel);

    dim3 g3(128, 4);
    out_proj_kernel<<<g3, 256>>>(opw, opb, out);
}

// round 3
// speedup vs baseline: 1.6308x; 1.6308x over previous
#include <cuda_runtime.h>
#include <math.h>

#define L_DIM 2048
#define S_DIM 2048
#define N_B   4
#define E_DIM 256
#define H_N   8
#define HD_N  32
#define NH_N  32
#define SCALING 0.17677669529663687f   // 32^-0.5

// Scratch (allocation-free rule: __device__ globals)
__device__ float g_q[(size_t)NH_N * L_DIM * HD_N];      // (NH, L, HD), pre-scaled + bias
__device__ float g_k[(size_t)NH_N * S_DIM * HD_N];      // (NH, S, HD)
__device__ float g_v[(size_t)NH_N * S_DIM * HD_N];      // (NH, S, HD)
__device__ float g_attn[(size_t)L_DIM * N_B * E_DIM];   // (L*N, E)

// ---------------------------------------------------------------------------
// QKV projection: C[m][e] = sum_k A[m][k] * W[z*E+e][k] + bias[z*E+e], scaled
// for z==0 (query). Output scattered to (NH, L, HD) layout.
// Grid: (M/64=128, E/64=4, 3), 256 threads, 64x64 tile, 4x4 microtile.
// ---------------------------------------------------------------------------
__global__ __launch_bounds__(256)
void qkv_proj_kernel(const float* __restrict__ q_in,
                     const float* __restrict__ k_in,
                     const float* __restrict__ v_in,
                     const float* __restrict__ W,
                     const float* __restrict__ bias)
{
    __shared__ float sA[16][68];   // [k][m], pad 68 (16B-aligned float4 rows)
    __shared__ float sB[16][68];   // [k][n]

    const int z = blockIdx.z;
    const float* A  = (z == 0) ? q_in : (z == 1) ? k_in : v_in;
    const float* Wz = W + (size_t)z * E_DIM * E_DIM;
    const float* bz = bias + z * E_DIM;
    float* Cz = (z == 0) ? g_q : (z == 1) ? g_k : g_v;
    const float scale = (z == 0) ? SCALING : 1.0f;

    const int tid = threadIdx.x;
    const int m0 = blockIdx.x * 64;
    const int n0 = blockIdx.y * 64;
    const int lr = tid >> 2;           // 0..63 (load row)
    const int lc = (tid & 3) << 2;     // 0,4,8,12 (load col base)
    const int ty = tid >> 4;           // 0..15 row group
    const int tx = tid & 15;           // 0..15 col group

    float acc[4][4];
#pragma unroll
    for (int i = 0; i < 4; i++)
#pragma unroll
        for (int j = 0; j < 4; j++) acc[i][j] = 0.f;

    for (int kb = 0; kb < E_DIM; kb += 16) {
        float4 av = *(const float4*)(A  + (size_t)(m0 + lr) * E_DIM + kb + lc);
        float4 bv = *(const float4*)(Wz + (size_t)(n0 + lr) * E_DIM + kb + lc);
        __syncthreads();
        sA[lc + 0][lr] = av.x; sA[lc + 1][lr] = av.y;
        sA[lc + 2][lr] = av.z; sA[lc + 3][lr] = av.w;
        sB[lc + 0][lr] = bv.x; sB[lc + 1][lr] = bv.y;
        sB[lc + 2][lr] = bv.z; sB[lc + 3][lr] = bv.w;
        __syncthreads();
#pragma unroll
        for (int kk = 0; kk < 16; kk++) {
            float4 a = *(const float4*)&sA[kk][ty << 2];
            float4 b = *(const float4*)&sB[kk][tx << 2];
            acc[0][0] += a.x * b.x; acc[0][1] += a.x * b.y; acc[0][2] += a.x * b.z; acc[0][3] += a.x * b.w;
            acc[1][0] += a.y * b.x; acc[1][1] += a.y * b.y; acc[1][2] += a.y * b.z; acc[1][3] += a.y * b.w;
            acc[2][0] += a.z * b.x; acc[2][1] += a.z * b.y; acc[2][2] += a.z * b.z; acc[2][3] += a.z * b.w;
            acc[3][0] += a.w * b.x; acc[3][1] += a.w * b.y; acc[3][2] += a.w * b.z; acc[3][3] += a.w * b.w;
        }
    }

    const int e0 = n0 + (tx << 2);
    float4 b4 = *(const float4*)(bz + e0);
    const int h = e0 >> 5, d = e0 & 31;     // 4 cols stay inside one head (32|4)
#pragma unroll
    for (int i = 0; i < 4; i++) {
        const int m = m0 + (ty << 2) + i;
        const int l = m >> 2, n = m & 3;    // m = l*N + n
        const int bh = n * H_N + h;
        float4 o;
        o.x = (acc[i][0] + b4.x) * scale;
        o.y = (acc[i][1] + b4.y) * scale;
        o.z = (acc[i][2] + b4.z) * scale;
        o.w = (acc[i][3] + b4.w) * scale;
        *(float4*)(Cz + ((size_t)bh * L_DIM + l) * HD_N + d) = o;
    }
}

// ---------------------------------------------------------------------------
// Attention: per CTA one (bh, 64-row L tile). Stream S in 64-col chunks.
// rel matrix streamed straight from gmem (zero reuse). Online softmax.
// Grid: (L/64=32, NH=32), 256 threads.
// Thread map: rg=tid>>4 owns 4 rows; cg=tid&15 owns 4 score cols and
// 2 output dims. Row reductions: 16-lane (half-warp) shfl.
// Loads: each thread covers row lr at cols {lc, lc+16} -> full 32 dims.
// ---------------------------------------------------------------------------
__global__ __launch_bounds__(256)
void attn_kernel(const float* __restrict__ rel)
{
    __shared__ float sQT[32][68];   // [d][row]
    __shared__ float sKT[32][68];   // [d][col]
    __shared__ float sV[64][36];    // [s][d]
    __shared__ float sP[64][68];    // [row][s]

    const int bh = blockIdx.y;
    const int l0 = blockIdx.x * 64;
    const int tid = threadIdx.x;
    const int rg = tid >> 4;
    const int cg = tid & 15;
    const int lr = tid >> 2;          // 0..63
    const int lc = (tid & 3) << 2;    // 0,4,8,12

    // Load Q tile transposed: sQT[d][r], both 16-col halves
    {
        const float* qrow = g_q + ((size_t)bh * L_DIM + l0 + lr) * HD_N;
        float4 q0 = *(const float4*)(qrow + lc);
        float4 q1 = *(const float4*)(qrow + lc + 16);
        sQT[lc + 0][lr] = q0.x; sQT[lc + 1][lr] = q0.y;
        sQT[lc + 2][lr] = q0.z; sQT[lc + 3][lr] = q0.w;
        sQT[lc + 16][lr] = q1.x; sQT[lc + 17][lr] = q1.y;
        sQT[lc + 18][lr] = q1.z; sQT[lc + 19][lr] = q1.w;
    }

    float O[4][2];
    float mrow[4], lrow[4];
#pragma unroll
    for (int i = 0; i < 4; i++) {
        O[i][0] = 0.f; O[i][1] = 0.f;
        mrow[i] = -INFINITY; lrow[i] = 0.f;
    }

    const float* relBase = rel + ((size_t)bh * L_DIM + (l0 + (rg << 2))) * S_DIM + (cg << 2);

    for (int s0 = 0; s0 < S_DIM; s0 += 64) {
        __syncthreads();   // prev-iter AV reads of sV/sP done before overwrite
        {
            const float* krow = g_k + ((size_t)bh * S_DIM + s0 + lr) * HD_N;
            float4 k0 = *(const float4*)(krow + lc);
            float4 k1 = *(const float4*)(krow + lc + 16);
            sKT[lc + 0][lr] = k0.x; sKT[lc + 1][lr] = k0.y;
            sKT[lc + 2][lr] = k0.z; sKT[lc + 3][lr] = k0.w;
            sKT[lc + 16][lr] = k1.x; sKT[lc + 17][lr] = k1.y;
            sKT[lc + 18][lr] = k1.z; sKT[lc + 19][lr] = k1.w;
            const float* vrow = g_v + ((size_t)bh * S_DIM + s0 + lr) * HD_N;
            *(float4*)&sV[lr][lc]      = *(const float4*)(vrow + lc);
            *(float4*)&sV[lr][lc + 16] = *(const float4*)(vrow + lc + 16);
        }
        __syncthreads();

        // ---- scores: acc = rel + q·k (q pre-scaled) ----
        float acc[4][4];
#pragma unroll
        for (int i = 0; i < 4; i++) {
            float4 rv = *(const float4*)(relBase + (size_t)i * S_DIM + s0);
            acc[i][0] = rv.x; acc[i][1] = rv.y; acc[i][2] = rv.z; acc[i][3] = rv.w;
        }
#pragma unroll
        for (int k = 0; k < 32; k++) {
            float4 a = *(const float4*)&sQT[k][rg << 2];
            float4 b = *(const float4*)&sKT[k][cg << 2];
            acc[0][0] += a.x * b.x; acc[0][1] += a.x * b.y; acc[0][2] += a.x * b.z; acc[0][3] += a.x * b.w;
            acc[1][0] += a.y * b.x; acc[1][1] += a.y * b.y; acc[1][2] += a.y * b.z; acc[1][3] += a.y * b.w;
            acc[2][0] += a.z * b.x; acc[2][1] += a.z * b.y; acc[2][2] += a.z * b.z; acc[2][3] += a.z * b.w;
            acc[3][0] += a.w * b.x; acc[3][1] += a.w * b.y; acc[3][2] += a.w * b.z; acc[3][3] += a.w * b.w;
        }

        // ---- online softmax (per row, reduce over 16 lanes of a half-warp) ----
#pragma unroll
        for (int i = 0; i < 4; i++) {
            float mx = fmaxf(fmaxf(acc[i][0], acc[i][1]), fmaxf(acc[i][2], acc[i][3]));
#pragma unroll
            for (int o = 8; o > 0; o >>= 1)
                mx = fmaxf(mx, __shfl_xor_sync(0xffffffffu, mx, o));
            const float mnew = fmaxf(mrow[i], mx);
            float p0 = __expf(acc[i][0] - mnew);
            float p1 = __expf(acc[i][1] - mnew);
            float p2 = __expf(acc[i][2] - mnew);
            float p3 = __expf(acc[i][3] - mnew);
            float sum = (p0 + p1) + (p2 + p3);
#pragma unroll
            for (int o = 8; o > 0; o >>= 1)
                sum += __shfl_xor_sync(0xffffffffu, sum, o);
            const float fac = __expf(mrow[i] - mnew);
            lrow[i] = lrow[i] * fac + sum;
            mrow[i] = mnew;
            O[i][0] *= fac; O[i][1] *= fac;
            *(float4*)&sP[(rg << 2) + i][cg << 2] = make_float4(p0, p1, p2, p3);
        }
        __syncthreads();

        // ---- AV: O[i][jd] += sum_s P[r][s] * V[s][d0+jd] ----
        const int d0 = cg << 1;
#pragma unroll
        for (int s = 0; s < 64; s += 4) {
            float2 v0 = *(const float2*)&sV[s + 0][d0];
            float2 v1 = *(const float2*)&sV[s + 1][d0];
            float2 v2 = *(const float2*)&sV[s + 2][d0];
            float2 v3 = *(const float2*)&sV[s + 3][d0];
#pragma unroll
            for (int i = 0; i < 4; i++) {
                float4 p = *(const float4*)&sP[(rg << 2) + i][s];
                O[i][0] += p.x * v0.x + p.y * v1.x + p.z * v2.x + p.w * v3.x;
                O[i][1] += p.x * v0.y + p.y * v1.y + p.z * v2.y + p.w * v3.y;
            }
        }
    }

    // ---- epilogue: normalize, write (L*N, E) layout ----
    const int n = bh >> 3, h = bh & 7;
#pragma unroll
    for (int i = 0; i < 4; i++) {
        const int l = l0 + (rg << 2) + i;
        const float inv = 1.0f / lrow[i];
        float2 o2 = make_float2(O[i][0] * inv, O[i][1] * inv);
        *(float2*)(g_attn + ((size_t)l * N_B + n) * E_DIM + h * HD_N + (cg << 1)) = o2;
    }
}

// ---------------------------------------------------------------------------
// Output projection: out[m][e] = sum_k attn[m][k] * Wo[e][k] + bo[e]
// Grid: (128, 4), 256 threads.
// ---------------------------------------------------------------------------
__global__ __launch_bounds__(256)
void out_proj_kernel(const float* __restrict__ W,
                     const float* __restrict__ bias,
                     float* __restrict__ out)
{
    __shared__ float sA[16][68];
    __shared__ float sB[16][68];

    const int tid = threadIdx.x;
    const int m0 = blockIdx.x * 64;
    const int n0 = blockIdx.y * 64;
    const int lr = tid >> 2;
    const int lc = (tid & 3) << 2;
    const int ty = tid >> 4;
    const int tx = tid & 15;

    float acc[4][4];
#pragma unroll
    for (int i = 0; i < 4; i++)
#pragma unroll
        for (int j = 0; j < 4; j++) acc[i][j] = 0.f;

    for (int kb = 0; kb < E_DIM; kb += 16) {
        float4 av = *(const float4*)(g_attn + (size_t)(m0 + lr) * E_DIM + kb + lc);
        float4 bv = *(const float4*)(W      + (size_t)(n0 + lr) * E_DIM + kb + lc);
        __syncthreads();
        sA[lc + 0][lr] = av.x; sA[lc + 1][lr] = av.y;
        sA[lc + 2][lr] = av.z; sA[lc + 3][lr] = av.w;
        sB[lc + 0][lr] = bv.x; sB[lc + 1][lr] = bv.y;
        sB[lc + 2][lr] = bv.z; sB[lc + 3][lr] = bv.w;
        __syncthreads();
#pragma unroll
        for (int kk = 0; kk < 16; kk++) {
            float4 a = *(const float4*)&sA[kk][ty << 2];
            float4 b = *(const float4*)&sB[kk][tx << 2];
            acc[0][0] += a.x * b.x; acc[0][1] += a.x * b.y; acc[0][2] += a.x * b.z; acc[0][3] += a.x * b.w;
            acc[1][0] += a.y * b.x; acc[1][1] += a.y * b.y; acc[1][2] += a.y * b.z; acc[1][3] += a.y * b.w;
            acc[2][0] += a.z * b.x; acc[2][1] += a.z * b.y; acc[2][2] += a.z * b.z; acc[2][3] += a.z * b.w;
            acc[3][0] += a.w * b.x; acc[3][1] += a.w * b.y; acc[3][2] += a.w * b.z; acc[3][3] += a.w * b.w;
        }
    }

    const int e0 = n0 + (tx << 2);
    float4 b4 = *(const float4*)(bias + e0);
#pragma unroll
    for (int i = 0; i < 4; i++) {
        const int m = m0 + (ty << 2) + i;
        float4 o;
        o.x = acc[i][0] + b4.x;
        o.y = acc[i][1] + b4.y;
        o.z = acc[i][2] + b4.z;
        o.w = acc[i][3] + b4.w;
        *(float4*)(out + (size_t)m * E_DIM + e0) = o;
    }
}

// ---------------------------------------------------------------------------
extern "C" void kernel_launch(void* const* d_in, const int* in_sizes, int n_in,
                              void* d_out, int out_size)
{
    const float* query = (const float*)d_in[0];
    const float* key   = (const float*)d_in[1];
    const float* value = (const float*)d_in[2];
    const float* rel   = (const float*)d_in[3];
    const float* ipw   = (const float*)d_in[4];
    const float* ipb   = (const float*)d_in[5];
    const float* opw   = (const float*)d_in[6];
    const float* opb   = (const float*)d_in[7];
    float* out = (float*)d_out;

    dim3 g1(128, 4, 3);
    qkv_proj_kernel<<<g1, 256>>>(query, key, value, ipw, ipb);

    dim3 g2(32, 32);   // x = L tiles (fast) so same-bh CTAs share K/V in L2
    attn_kernel<<<g2, 256>>>(rel);

    dim3 g3(128, 4);
    out_proj_kernel<<<g3, 256>>>(opw, opb, out);
}

// round 5
// speedup vs baseline: 3.2424x; 1.9882x over previous
#include <cuda_runtime.h>
#include <cuda_bf16.h>
#include <math.h>
#include <stdint.h>

#define L_DIM 2048
#define S_DIM 2048
#define N_B   4
#define E_DIM 256
#define H_N   8
#define HD_N  32
#define NH_N  32
#define SCALING 0.17677669529663687f

// bf16 split layout per (bh,row): 128B = [hi d0..31 (64B) | lo d0..31 (64B)]
__device__ __align__(128) uint8_t g_qb[(size_t)NH_N * L_DIM * 128];
__device__ __align__(128) uint8_t g_kb[(size_t)NH_N * S_DIM * 128];
__device__ __align__(128) uint8_t g_vb[(size_t)NH_N * S_DIM * 128];
__device__ float g_attn[(size_t)L_DIM * N_B * E_DIM];

// ---------------- helpers ----------------
__device__ __forceinline__ uint32_t smem_u32(const void* p) {
    uint32_t a;
    asm("{ .reg .u64 t; cvta.to.shared.u64 t, %1; cvt.u32.u64 %0, t; }" : "=r"(a) : "l"(p));
    return a;
}
__device__ __forceinline__ uint32_t pack2(__nv_bfloat16 a, __nv_bfloat16 b) {
    return (uint32_t)__bfloat16_as_ushort(a) | ((uint32_t)__bfloat16_as_ushort(b) << 16);
}
__device__ __forceinline__ uint32_t packf2(float a, float b) {
    __nv_bfloat162 t = __floats2bfloat162_rn(a, b);
    return *(uint32_t*)&t;
}

#define LDSM4(R, addr)                                                          \
    asm volatile("ldmatrix.sync.aligned.m8n8.x4.shared.b16 {%0,%1,%2,%3}, [%4];" \
        : "=r"((R)[0]), "=r"((R)[1]), "=r"((R)[2]), "=r"((R)[3]) : "r"(addr))
#define LDSM4T(R, addr)                                                         \
    asm volatile("ldmatrix.sync.aligned.m8n8.x4.trans.shared.b16 {%0,%1,%2,%3}, [%4];" \
        : "=r"((R)[0]), "=r"((R)[1]), "=r"((R)[2]), "=r"((R)[3]) : "r"(addr))

__device__ __forceinline__ void mma16816(float c[4], const uint32_t a[4],
                                         uint32_t b0, uint32_t b1) {
    asm volatile("mma.sync.aligned.m16n8k16.row.col.f32.bf16.bf16.f32 "
        "{%0,%1,%2,%3}, {%4,%5,%6,%7}, {%8,%9}, {%0,%1,%2,%3};"
        : "+f"(c[0]), "+f"(c[1]), "+f"(c[2]), "+f"(c[3])
        : "r"(a[0]), "r"(a[1]), "r"(a[2]), "r"(a[3]), "r"(b0), "r"(b1));
}

// ---------------- QKV projection (fp32 GEMM, bf16-split epilogue) ----------------
__global__ __launch_bounds__(256)
void qkv_proj_kernel(const float* __restrict__ q_in, const float* __restrict__ k_in,
                     const float* __restrict__ v_in, const float* __restrict__ W,
                     const float* __restrict__ bias)
{
    __shared__ float sA[16][68];
    __shared__ float sB[16][68];

    const int z = blockIdx.z;
    const float* A  = (z == 0) ? q_in : (z == 1) ? k_in : v_in;
    const float* Wz = W + (size_t)z * E_DIM * E_DIM;
    const float* bz = bias + z * E_DIM;
    uint8_t* Cz = (z == 0) ? g_qb : (z == 1) ? g_kb : g_vb;
    const float scale = (z == 0) ? SCALING : 1.0f;

    const int tid = threadIdx.x;
    const int m0 = blockIdx.x * 64, n0 = blockIdx.y * 64;
    const int lr = tid >> 2, lc = (tid & 3) << 2;
    const int ty = tid >> 4, tx = tid & 15;

    float acc[4][4];
#pragma unroll
    for (int i = 0; i < 4; i++)
#pragma unroll
        for (int j = 0; j < 4; j++) acc[i][j] = 0.f;

    for (int kb = 0; kb < E_DIM; kb += 16) {
        float4 av = *(const float4*)(A  + (size_t)(m0 + lr) * E_DIM + kb + lc);
        float4 bv = *(const float4*)(Wz + (size_t)(n0 + lr) * E_DIM + kb + lc);
        __syncthreads();
        sA[lc+0][lr]=av.x; sA[lc+1][lr]=av.y; sA[lc+2][lr]=av.z; sA[lc+3][lr]=av.w;
        sB[lc+0][lr]=bv.x; sB[lc+1][lr]=bv.y; sB[lc+2][lr]=bv.z; sB[lc+3][lr]=bv.w;
        __syncthreads();
#pragma unroll
        for (int kk = 0; kk < 16; kk++) {
            float4 a = *(const float4*)&sA[kk][ty << 2];
            float4 b = *(const float4*)&sB[kk][tx << 2];
            acc[0][0]+=a.x*b.x; acc[0][1]+=a.x*b.y; acc[0][2]+=a.x*b.z; acc[0][3]+=a.x*b.w;
            acc[1][0]+=a.y*b.x; acc[1][1]+=a.y*b.y; acc[1][2]+=a.y*b.z; acc[1][3]+=a.y*b.w;
            acc[2][0]+=a.z*b.x; acc[2][1]+=a.z*b.y; acc[2][2]+=a.z*b.z; acc[2][3]+=a.z*b.w;
            acc[3][0]+=a.w*b.x; acc[3][1]+=a.w*b.y; acc[3][2]+=a.w*b.z; acc[3][3]+=a.w*b.w;
        }
    }

    const int e0 = n0 + (tx << 2);
    float4 b4 = *(const float4*)(bz + e0);
    const int h = e0 >> 5, d = e0 & 31;
#pragma unroll
    for (int i = 0; i < 4; i++) {
        const int m = m0 + (ty << 2) + i;
        const int l = m >> 2, n = m & 3;
        const int bh = n * H_N + h;
        float v0 = (acc[i][0] + b4.x) * scale;
        float v1 = (acc[i][1] + b4.y) * scale;
        float v2 = (acc[i][2] + b4.z) * scale;
        float v3 = (acc[i][3] + b4.w) * scale;
        __nv_bfloat16 h0 = __float2bfloat16(v0), h1 = __float2bfloat16(v1);
        __nv_bfloat16 h2 = __float2bfloat16(v2), h3 = __float2bfloat16(v3);
        __nv_bfloat16 l0b = __float2bfloat16(v0 - __bfloat162float(h0));
        __nv_bfloat16 l1b = __float2bfloat16(v1 - __bfloat162float(h1));
        __nv_bfloat16 l2b = __float2bfloat16(v2 - __bfloat162float(h2));
        __nv_bfloat16 l3b = __float2bfloat16(v3 - __bfloat162float(h3));
        uint8_t* row = Cz + ((size_t)bh * L_DIM + l) * 128;
        *(uint2*)(row + 2*d)      = make_uint2(pack2(h0,h1), pack2(h2,h3));
        *(uint2*)(row + 64 + 2*d) = make_uint2(pack2(l0b,l1b), pack2(l2b,l3b));
    }
}

// ---------------- Attention: FA2-style HMMA, grid (32, 32), 128 threads ----------------
// smem pitch 144B: ldmatrix row addresses land on distinct 4-bank groups (4r mod 32).
#define PITCH 144

__global__ __launch_bounds__(128)
void attn_mma_kernel(const float* __restrict__ rel)
{
    __shared__ __align__(16) uint8_t sQ[64 * PITCH];
    __shared__ __align__(16) uint8_t sK[64 * PITCH];
    __shared__ __align__(16) uint8_t sV[64 * PITCH];

    const int tid  = threadIdx.x;
    const int wid  = tid >> 5;
    const int lane = tid & 31;
    const int bh = blockIdx.y;
    const int l0 = blockIdx.x * 64;
    const int WROW = wid * 16;    // warp's 16 rows within the 64-row tile

    // ---- stage Q tile (64 rows x 128B) into smem ----
    {
        const uint4* qs = (const uint4*)(g_qb + ((size_t)bh * L_DIM + l0) * 128);
#pragma unroll
        for (int j = 0; j < 4; j++) {
            int i = tid + j * 128;             // 0..511
            *(uint4*)(sQ + (i >> 3) * PITCH + (i & 7) * 16) = qs[i];
        }
    }
    __syncthreads();

    // ---- Q A-fragments (persistent): hi k0-15, hi k16-31, lo k0-15, lo k16-31 ----
    uint32_t qh0[4], qh1[4], ql0[4], ql1[4];
    {
        uint32_t qaddr = smem_u32(sQ) + (WROW + (lane & 15)) * PITCH + (lane >> 4) * 16;
        LDSM4(qh0, qaddr);
        LDSM4(qh1, qaddr + 32);
        LDSM4(ql0, qaddr + 64);
        LDSM4(ql1, qaddr + 96);
    }

    float O[4][4];     // 4 d-tiles (d = 8*dt + 2*(lane&3)), rows lane/4 and lane/4+8
#pragma unroll
    for (int t = 0; t < 4; t++)
#pragma unroll
        for (int j = 0; j < 4; j++) O[t][j] = 0.f;
    float rsum0 = 0.f, rsum1 = 0.f;

    const int qrow = lane >> 2;                 // 0..7
    const int qcol = (lane & 3) << 1;           // 0,2,4,6
    const float* rel0 = rel + ((size_t)bh * L_DIM + l0 + WROW + qrow) * S_DIM;
    const float* rel8 = rel0 + (size_t)8 * S_DIM;

    const uint4* ksrc = (const uint4*)(g_kb + (size_t)bh * S_DIM * 128);
    const uint4* vsrc = (const uint4*)(g_vb + (size_t)bh * S_DIM * 128);
    const uint32_t sKb = smem_u32(sK), sVb = smem_u32(sV);

    for (int c = 0; c < S_DIM / 64; ++c) {
        const int s0 = c * 64;
        __syncthreads();   // prior iteration done with sK/sV
#pragma unroll
        for (int j = 0; j < 4; j++) {
            int i = tid + j * 128;             // 0..511
            uint32_t dst = (i >> 3) * PITCH + (i & 7) * 16;
            *(uint4*)(sK + dst) = ksrc[c * 512 + i];
            *(uint4*)(sV + dst) = vsrc[c * 512 + i];
        }
        __syncthreads();

        uint32_t aPhi[4][4], aPlo[4][4];

        // ---- QK^T + rel + exp, per n-pair (16 s-cols each) ----
#pragma unroll
        for (int np = 0; np < 4; np++) {
            // K B-fragments for this n-pair
            uint32_t kaddr = sKb + (16*np + (lane & 7) + ((lane >> 4) << 3)) * PITCH
                           + ((lane >> 3) & 1) * 16;
            uint32_t kh0[4], kh1[4], kl0[4], kl1[4];
            LDSM4(kh0, kaddr);
            LDSM4(kh1, kaddr + 32);
            LDSM4(kl0, kaddr + 64);
            LDSM4(kl1, kaddr + 96);

            // C init from rel (fragment-shaped direct loads)
            const int colA = s0 + 16*np + qcol;
            float cA[4], cB[4];
            {
                float2 t0 = *(const float2*)(rel0 + colA);
                float2 t1 = *(const float2*)(rel8 + colA);
                float2 t2 = *(const float2*)(rel0 + colA + 8);
                float2 t3 = *(const float2*)(rel8 + colA + 8);
                cA[0]=t0.x; cA[1]=t0.y; cA[2]=t1.x; cA[3]=t1.y;
                cB[0]=t2.x; cB[1]=t2.y; cB[2]=t3.x; cB[3]=t3.y;
            }
            // 3-term split QK
            mma16816(cA, qh0, kh0[0], kh0[1]);
            mma16816(cA, qh1, kh1[0], kh1[1]);
            mma16816(cA, qh0, kl0[0], kl0[1]);
            mma16816(cA, qh1, kl1[0], kl1[1]);
            mma16816(cA, ql0, kh0[0], kh0[1]);
            mma16816(cA, ql1, kh1[0], kh1[1]);

            mma16816(cB, qh0, kh0[2], kh0[3]);
            mma16816(cB, qh1, kh1[2], kh1[3]);
            mma16816(cB, qh0, kl0[2], kl0[3]);
            mma16816(cB, qh1, kl1[2], kl1[3]);
            mma16816(cB, ql0, kh0[2], kh0[3]);
            mma16816(cB, ql1, kh1[2], kh1[3]);

            // exp (no max-sub; scores bounded) + row sums + hi/lo pack
            float pA0 = __expf(cA[0]), pA1 = __expf(cA[1]);
            float pA2 = __expf(cA[2]), pA3 = __expf(cA[3]);
            float pB0 = __expf(cB[0]), pB1 = __expf(cB[1]);
            float pB2 = __expf(cB[2]), pB3 = __expf(cB[3]);
            rsum0 += (pA0 + pA1) + (pB0 + pB1);
            rsum1 += (pA2 + pA3) + (pB2 + pB3);

            uint32_t u0 = packf2(pA0, pA1), u1 = packf2(pA2, pA3);
            uint32_t u2 = packf2(pB0, pB1), u3 = packf2(pB2, pB3);
            aPhi[np][0] = u0; aPhi[np][1] = u1; aPhi[np][2] = u2; aPhi[np][3] = u3;
            aPlo[np][0] = packf2(pA0 - __uint_as_float(u0 << 16),
                                 pA1 - __uint_as_float(u0 & 0xffff0000u));
            aPlo[np][1] = packf2(pA2 - __uint_as_float(u1 << 16),
                                 pA3 - __uint_as_float(u1 & 0xffff0000u));
            aPlo[np][2] = packf2(pB0 - __uint_as_float(u2 << 16),
                                 pB1 - __uint_as_float(u2 & 0xffff0000u));
            aPlo[np][3] = packf2(pB2 - __uint_as_float(u3 << 16),
                                 pB3 - __uint_as_float(u3 & 0xffff0000u));
        }

        // ---- AV: O += Phi*Vhi + Phi*Vlo + Plo*Vhi, per k-step (16 s each) ----
#pragma unroll
        for (int j = 0; j < 4; j++) {
            uint32_t vaddr = sVb + (16*j + (lane & 15)) * PITCH + (lane >> 4) * 16;
            uint32_t vh0[4], vh1[4], vl0[4], vl1[4];
            LDSM4T(vh0, vaddr);        // hi d0-15: (r0,r1)=d0-7, (r2,r3)=d8-15
            LDSM4T(vh1, vaddr + 32);   // hi d16-31
            LDSM4T(vl0, vaddr + 64);   // lo d0-15
            LDSM4T(vl1, vaddr + 96);   // lo d16-31

            mma16816(O[0], aPhi[j], vh0[0], vh0[1]);
            mma16816(O[0], aPhi[j], vl0[0], vl0[1]);
            mma16816(O[0], aPlo[j], vh0[0], vh0[1]);

            mma16816(O[1], aPhi[j], vh0[2], vh0[3]);
            mma16816(O[1], aPhi[j], vl0[2], vl0[3]);
            mma16816(O[1], aPlo[j], vh0[2], vh0[3]);

            mma16816(O[2], aPhi[j], vh1[0], vh1[1]);
            mma16816(O[2], aPhi[j], vl1[0], vl1[1]);
            mma16816(O[2], aPlo[j], vh1[0], vh1[1]);

            mma16816(O[3], aPhi[j], vh1[2], vh1[3]);
            mma16816(O[3], aPhi[j], vl1[2], vl1[3]);
            mma16816(O[3], aPlo[j], vh1[2], vh1[3]);
        }
    }

    // ---- epilogue: reduce row sums over quad, normalize, write ----
    rsum0 += __shfl_xor_sync(0xffffffffu, rsum0, 1);
    rsum0 += __shfl_xor_sync(0xffffffffu, rsum0, 2);
    rsum1 += __shfl_xor_sync(0xffffffffu, rsum1, 1);
    rsum1 += __shfl_xor_sync(0xffffffffu, rsum1, 2);
    const float inv0 = 1.0f / rsum0, inv1 = 1.0f / rsum1;

    const int n = bh >> 3, h = bh & 7;
    const int r = l0 + WROW + qrow;
    float* base0 = g_attn + ((size_t)r * N_B + n) * E_DIM + h * HD_N + qcol;
    float* base8 = base0 + (size_t)8 * N_B * E_DIM;
#pragma unroll
    for (int t = 0; t < 4; t++) {
        *(float2*)(base0 + t * 8) = make_float2(O[t][0] * inv0, O[t][1] * inv0);
        *(float2*)(base8 + t * 8) = make_float2(O[t][2] * inv1, O[t][3] * inv1);
    }
}

// ---------------- Output projection (fp32) ----------------
__global__ __launch_bounds__(256)
void out_proj_kernel(const float* __restrict__ W, const float* __restrict__ bias,
                     float* __restrict__ out)
{
    __shared__ float sA[16][68];
    __shared__ float sB[16][68];
    const int tid = threadIdx.x;
    const int m0 = blockIdx.x * 64, n0 = blockIdx.y * 64;
    const int lr = tid >> 2, lc = (tid & 3) << 2;
    const int ty = tid >> 4, tx = tid & 15;

    float acc[4][4];
#pragma unroll
    for (int i = 0; i < 4; i++)
#pragma unroll
        for (int j = 0; j < 4; j++) acc[i][j] = 0.f;

    for (int kb = 0; kb < E_DIM; kb += 16) {
        float4 av = *(const float4*)(g_attn + (size_t)(m0 + lr) * E_DIM + kb + lc);
        float4 bv = *(const float4*)(W      + (size_t)(n0 + lr) * E_DIM + kb + lc);
        __syncthreads();
        sA[lc+0][lr]=av.x; sA[lc+1][lr]=av.y; sA[lc+2][lr]=av.z; sA[lc+3][lr]=av.w;
        sB[lc+0][lr]=bv.x; sB[lc+1][lr]=bv.y; sB[lc+2][lr]=bv.z; sB[lc+3][lr]=bv.w;
        __syncthreads();
#pragma unroll
        for (int kk = 0; kk < 16; kk++) {
            float4 a = *(const float4*)&sA[kk][ty << 2];
            float4 b = *(const float4*)&sB[kk][tx << 2];
            acc[0][0]+=a.x*b.x; acc[0][1]+=a.x*b.y; acc[0][2]+=a.x*b.z; acc[0][3]+=a.x*b.w;
            acc[1][0]+=a.y*b.x; acc[1][1]+=a.y*b.y; acc[1][2]+=a.y*b.z; acc[1][3]+=a.y*b.w;
            acc[2][0]+=a.z*b.x; acc[2][1]+=a.z*b.y; acc[2][2]+=a.z*b.z; acc[2][3]+=a.z*b.w;
            acc[3][0]+=a.w*b.x; acc[3][1]+=a.w*b.y; acc[3][2]+=a.w*b.z; acc[3][3]+=a.w*b.w;
        }
    }
    const int e0 = n0 + (tx << 2);
    float4 b4 = *(const float4*)(bias + e0);
#pragma unroll
    for (int i = 0; i < 4; i++) {
        const int m = m0 + (ty << 2) + i;
        float4 o;
        o.x = acc[i][0] + b4.x; o.y = acc[i][1] + b4.y;
        o.z = acc[i][2] + b4.z; o.w = acc[i][3] + b4.w;
        *(float4*)(out + (size_t)m * E_DIM + e0) = o;
    }
}

// ---------------------------------------------------------------------------
extern "C" void kernel_launch(void* const* d_in, const int* in_sizes, int n_in,
                              void* d_out, int out_size)
{
    const float* query = (const float*)d_in[0];
    const float* key   = (const float*)d_in[1];
    const float* value = (const float*)d_in[2];
    const float* rel   = (const float*)d_in[3];
    const float* ipw   = (const float*)d_in[4];
    const float* ipb   = (const float*)d_in[5];
    const float* opw   = (const float*)d_in[6];
    const float* opb   = (const float*)d_in[7];
    float* out = (float*)d_out;

    dim3 g1(128, 4, 3);
    qkv_proj_kernel<<<g1, 256>>>(query, key, value, ipw, ipb);

    dim3 g2(32, 32);
    attn_mma_kernel<<<g2, 128>>>(rel);

    dim3 g3(128, 4);
    out_proj_kernel<<<g3, 256>>>(opw, opb, out);
}

// round 6
// speedup vs baseline: 3.9519x; 1.2188x over previous
#include <cuda_runtime.h>
#include <cuda_bf16.h>
#include <math.h>
#include <stdint.h>

#define L_DIM 2048
#define S_DIM 2048
#define N_B   4
#define E_DIM 256
#define H_N   8
#define HD_N  32
#define NH_N  32
#define SCALING 0.17677669529663687f

// q/k/v split layout per (bh,row): 128B = [hi d0..31 (64B) | lo d0..31 (64B)]
__device__ __align__(128) uint8_t g_qb[(size_t)NH_N * L_DIM * 128];
__device__ __align__(128) uint8_t g_kb[(size_t)NH_N * S_DIM * 128];
__device__ __align__(128) uint8_t g_vb[(size_t)NH_N * S_DIM * 128];
// generic split rows: 1KB = [hi 256 cols (512B) | lo (512B)]
__device__ __align__(128) uint8_t g_insp[(size_t)3 * 8192 * 1024];   // q,k,v inputs
__device__ __align__(128) uint8_t g_wsp[(size_t)4 * 256 * 1024];     // Wq,Wk,Wv,Wo
__device__ __align__(128) uint8_t g_ao[(size_t)8192 * 1024];         // attn output

// ---------------- helpers ----------------
__device__ __forceinline__ uint32_t smem_u32(const void* p) {
    uint32_t a;
    asm("{ .reg .u64 t; cvta.to.shared.u64 t, %1; cvt.u32.u64 %0, t; }" : "=r"(a) : "l"(p));
    return a;
}
__device__ __forceinline__ uint32_t pack2(__nv_bfloat16 a, __nv_bfloat16 b) {
    return (uint32_t)__bfloat16_as_ushort(a) | ((uint32_t)__bfloat16_as_ushort(b) << 16);
}
__device__ __forceinline__ uint32_t packf2(float a, float b) {
    __nv_bfloat162 t = __floats2bfloat162_rn(a, b);
    return *(uint32_t*)&t;
}
__device__ __forceinline__ void split1(float v, uint32_t& hi16, uint32_t& lo16) {
    __nv_bfloat16 h = __float2bfloat16(v);
    __nv_bfloat16 l = __float2bfloat16(v - __bfloat162float(h));
    hi16 = __bfloat16_as_ushort(h);
    lo16 = __bfloat16_as_ushort(l);
}

#define LDSM4(R, addr)                                                          \
    asm volatile("ldmatrix.sync.aligned.m8n8.x4.shared.b16 {%0,%1,%2,%3}, [%4];" \
        : "=r"((R)[0]), "=r"((R)[1]), "=r"((R)[2]), "=r"((R)[3]) : "r"(addr))
#define LDSM4T(R, addr)                                                         \
    asm volatile("ldmatrix.sync.aligned.m8n8.x4.trans.shared.b16 {%0,%1,%2,%3}, [%4];" \
        : "=r"((R)[0]), "=r"((R)[1]), "=r"((R)[2]), "=r"((R)[3]) : "r"(addr))

__device__ __forceinline__ void mma16816(float c[4], const uint32_t a[4],
                                         uint32_t b0, uint32_t b1) {
    asm volatile("mma.sync.aligned.m16n8k16.row.col.f32.bf16.bf16.f32 "
        "{%0,%1,%2,%3}, {%4,%5,%6,%7}, {%8,%9}, {%0,%1,%2,%3};"
        : "+f"(c[0]), "+f"(c[1]), "+f"(c[2]), "+f"(c[3])
        : "r"(a[0]), "r"(a[1]), "r"(a[2]), "r"(a[3]), "r"(b0), "r"(b1));
}

// ---------------- conversion kernels (fp32 -> bf16 hi|lo split rows) ----------------
__global__ __launch_bounds__(256)
void convert_in_kernel(const float* __restrict__ q_in, const float* __restrict__ k_in,
                       const float* __restrict__ v_in)
{
    const int z = blockIdx.y;
    const float* src = (z == 0) ? q_in : (z == 1) ? k_in : v_in;
    uint8_t* dst = g_insp + (size_t)z * 8192 * 1024;
    size_t g = ((size_t)blockIdx.x * 256 + threadIdx.x) * 4;   // element index
    float4 v = *(const float4*)(src + g);
    uint32_t h0,l0,h1,l1,h2,l2,h3,l3;
    split1(v.x,h0,l0); split1(v.y,h1,l1); split1(v.z,h2,l2); split1(v.w,h3,l3);
    size_t row = g >> 8;
    int c = (int)(g & 255);
    uint8_t* rp = dst + row * 1024;
    *(uint2*)(rp + 2*c)       = make_uint2(h0 | (h1<<16), h2 | (h3<<16));
    *(uint2*)(rp + 512 + 2*c) = make_uint2(l0 | (l1<<16), l2 | (l3<<16));
}

__global__ __launch_bounds__(256)
void convert_w_kernel(const float* __restrict__ ipw, const float* __restrict__ opw)
{
    const int z = blockIdx.y;
    const float* src = (z < 3) ? (ipw + (size_t)z * 65536) : opw;
    uint8_t* dst = g_wsp + (size_t)z * 262144;
    size_t g = ((size_t)blockIdx.x * 256 + threadIdx.x) * 4;
    float4 v = *(const float4*)(src + g);
    uint32_t h0,l0,h1,l1,h2,l2,h3,l3;
    split1(v.x,h0,l0); split1(v.y,h1,l1); split1(v.z,h2,l2); split1(v.w,h3,l3);
    size_t row = g >> 8;
    int c = (int)(g & 255);
    uint8_t* rp = dst + row * 1024;
    *(uint2*)(rp + 2*c)       = make_uint2(h0 | (h1<<16), h2 | (h3<<16));
    *(uint2*)(rp + 512 + 2*c) = make_uint2(l0 | (l1<<16), l2 | (l3<<16));
}

// ---------------- HMMA projection GEMM ----------------
// C[m][e] = sum_k A[m][k] * W[e][k] (+bias, *scale), 3-term bf16 split.
// CTA: 128 thr (4 warps 2x2), tile 64m x 128n, K in 32-chunks, pitch-144 smem.
// mode 0: qkv -> split-scatter into g_qb/g_kb/g_vb (z = blockIdx.z)
// mode 1: out_proj -> fp32 d_out
#define PPITCH 144

__global__ __launch_bounds__(128)
void proj_mma_kernel(const float* __restrict__ bias_base, float* __restrict__ out,
                     int mode)
{
    __shared__ __align__(16) uint8_t sA[64 * PPITCH];
    __shared__ __align__(16) uint8_t sW[128 * PPITCH];

    const int tid  = threadIdx.x;
    const int wid  = tid >> 5;
    const int lane = tid & 31;
    const int z = blockIdx.z;
    const int m0 = blockIdx.x * 64;
    const int n0 = blockIdx.y * 128;
    const int wm = wid >> 1;          // 0,1 : 32-row half
    const int wn = wid & 1;           // 0,1 : 64-col half

    const uint8_t* A = (mode == 0) ? (g_insp + (size_t)z * 8192 * 1024) : g_ao;
    const uint8_t* W = g_wsp + (size_t)((mode == 0) ? z : 3) * 262144;
    const float* bias = bias_base + ((mode == 0) ? z * 256 : 0);
    const float scale = (mode == 0 && z == 0) ? SCALING : 1.0f;

    float acc[2][8][4];
#pragma unroll
    for (int a = 0; a < 2; a++)
#pragma unroll
        for (int t = 0; t < 8; t++)
#pragma unroll
            for (int j = 0; j < 4; j++) acc[a][t][j] = 0.f;

    const uint32_t sAb = smem_u32(sA), sWb = smem_u32(sW);

    for (int kc = 0; kc < 8; kc++) {            // k0 = kc*32
        const int koff = kc * 64;                // byte offset of hi slice in 1KB row
        __syncthreads();
        // stage A: 64 rows x (hi 64B + lo 64B)
#pragma unroll
        for (int j = 0; j < 4; j++) {
            int i = tid + j * 128;               // 0..511
            int row = i >> 3, seg = i & 7;
            const uint8_t* src = A + (size_t)(m0 + row) * 1024
                               + (seg < 4 ? koff + seg * 16 : 512 + koff + (seg - 4) * 16);
            uint8_t* dst = sA + row * PPITCH + (seg < 4 ? seg * 16 : 64 + (seg - 4) * 16);
            *(uint4*)dst = *(const uint4*)src;
        }
        // stage W: 128 rows
#pragma unroll
        for (int j = 0; j < 8; j++) {
            int i = tid + j * 128;               // 0..1023
            int row = i >> 3, seg = i & 7;
            const uint8_t* src = W + (size_t)(n0 + row) * 1024
                               + (seg < 4 ? koff + seg * 16 : 512 + koff + (seg - 4) * 16);
            uint8_t* dst = sW + row * PPITCH + (seg < 4 ? seg * 16 : 64 + (seg - 4) * 16);
            *(uint4*)dst = *(const uint4*)src;
        }
        __syncthreads();

#pragma unroll
        for (int ks = 0; ks < 2; ks++) {         // 16-k steps
            uint32_t ah[2][4], al[2][4];
#pragma unroll
            for (int am = 0; am < 2; am++) {
                uint32_t aaddr = sAb + (wm*32 + am*16 + (lane & 15)) * PPITCH
                               + ks*32 + (lane >> 4) * 16;
                LDSM4(ah[am], aaddr);
                LDSM4(al[am], aaddr + 64);
            }
            uint32_t bh[4][4], bl[4][4];
#pragma unroll
            for (int g = 0; g < 4; g++) {
                uint32_t baddr = sWb + (wn*64 + g*16 + (lane & 7) + ((lane >> 4) << 3)) * PPITCH
                               + ks*32 + ((lane >> 3) & 1) * 16;
                LDSM4(bh[g], baddr);
                LDSM4(bl[g], baddr + 64);
            }
#pragma unroll
            for (int am = 0; am < 2; am++)
#pragma unroll
                for (int g = 0; g < 4; g++) {
                    mma16816(acc[am][2*g+0], ah[am], bh[g][0], bh[g][1]);
                    mma16816(acc[am][2*g+0], ah[am], bl[g][0], bl[g][1]);
                    mma16816(acc[am][2*g+0], al[am], bh[g][0], bh[g][1]);
                    mma16816(acc[am][2*g+1], ah[am], bh[g][2], bh[g][3]);
                    mma16816(acc[am][2*g+1], ah[am], bl[g][2], bl[g][3]);
                    mma16816(acc[am][2*g+1], al[am], bh[g][2], bh[g][3]);
                }
        }
    }

    // ---- epilogue ----
    const int qrow = lane >> 2, qcol = (lane & 3) << 1;
    uint8_t* dstz = (z == 0) ? g_qb : (z == 1) ? g_kb : g_vb;
#pragma unroll
    for (int am = 0; am < 2; am++) {
        const int r0 = m0 + wm*32 + am*16 + qrow;
#pragma unroll
        for (int t = 0; t < 8; t++) {
            const int e = n0 + wn*64 + (t >> 1)*16 + (t & 1)*8 + qcol;
            const float b0 = bias[e], b1 = bias[e+1];
            float v00 = (acc[am][t][0] + b0) * scale;
            float v01 = (acc[am][t][1] + b1) * scale;
            float v10 = (acc[am][t][2] + b0) * scale;
            float v11 = (acc[am][t][3] + b1) * scale;
            if (mode == 0) {
                const int hh = e >> 5, d = e & 31;
#pragma unroll
                for (int half = 0; half < 2; half++) {
                    const int r = r0 + half * 8;
                    const float va = half ? v10 : v00;
                    const float vb = half ? v11 : v01;
                    const int l = r >> 2, nn = r & 3;
                    uint8_t* rp = dstz + ((size_t)(nn * H_N + hh) * L_DIM + l) * 128;
                    uint32_t ha,la,hb,lb;
                    split1(va, ha, la); split1(vb, hb, lb);
                    *(uint32_t*)(rp + 2*d)      = ha | (hb << 16);
                    *(uint32_t*)(rp + 64 + 2*d) = la | (lb << 16);
                }
            } else {
                *(float2*)(out + (size_t)r0 * E_DIM + e)       = make_float2(v00, v01);
                *(float2*)(out + (size_t)(r0+8) * E_DIM + e)   = make_float2(v10, v11);
            }
        }
    }
}

// ---------------- Attention: FA2-style HMMA, grid (32, 32), 128 threads ----------------
#define PITCH 144

__global__ __launch_bounds__(128)
void attn_mma_kernel(const float* __restrict__ rel)
{
    __shared__ __align__(16) uint8_t sQ[64 * PITCH];
    __shared__ __align__(16) uint8_t sK[64 * PITCH];
    __shared__ __align__(16) uint8_t sV[64 * PITCH];

    const int tid  = threadIdx.x;
    const int wid  = tid >> 5;
    const int lane = tid & 31;
    const int bh = blockIdx.y;
    const int l0 = blockIdx.x * 64;
    const int WROW = wid * 16;

    // stage Q tile
    {
        const uint4* qs = (const uint4*)(g_qb + ((size_t)bh * L_DIM + l0) * 128);
#pragma unroll
        for (int j = 0; j < 4; j++) {
            int i = tid + j * 128;
            *(uint4*)(sQ + (i >> 3) * PITCH + (i & 7) * 16) = qs[i];
        }
    }
    __syncthreads();

    uint32_t qh0[4], qh1[4], ql0[4], ql1[4];
    {
        uint32_t qaddr = smem_u32(sQ) + (WROW + (lane & 15)) * PITCH + (lane >> 4) * 16;
        LDSM4(qh0, qaddr);
        LDSM4(qh1, qaddr + 32);
        LDSM4(ql0, qaddr + 64);
        LDSM4(ql1, qaddr + 96);
    }

    float O[4][4];
#pragma unroll
    for (int t = 0; t < 4; t++)
#pragma unroll
        for (int j = 0; j < 4; j++) O[t][j] = 0.f;
    float rsum0 = 0.f, rsum1 = 0.f;

    const int qrow = lane >> 2;
    const int qcol = (lane & 3) << 1;
    const float* rel0 = rel + ((size_t)bh * L_DIM + l0 + WROW + qrow) * S_DIM;
    const float* rel8 = rel0 + (size_t)8 * S_DIM;

    const uint4* ksrc = (const uint4*)(g_kb + (size_t)bh * S_DIM * 128);
    const uint4* vsrc = (const uint4*)(g_vb + (size_t)bh * S_DIM * 128);
    const uint32_t sKb = smem_u32(sK), sVb = smem_u32(sV);

    for (int c = 0; c < S_DIM / 64; ++c) {
        const int s0 = c * 64;
        __syncthreads();
#pragma unroll
        for (int j = 0; j < 4; j++) {
            int i = tid + j * 128;
            uint32_t dst = (i >> 3) * PITCH + (i & 7) * 16;
            *(uint4*)(sK + dst) = ksrc[c * 512 + i];
            *(uint4*)(sV + dst) = vsrc[c * 512 + i];
        }
        __syncthreads();

        uint32_t aPhi[4][4], aPlo[4][4];

#pragma unroll
        for (int np = 0; np < 4; np++) {
            uint32_t kaddr = sKb + (16*np + (lane & 7) + ((lane >> 4) << 3)) * PITCH
                           + ((lane >> 3) & 1) * 16;
            uint32_t kh0[4], kh1[4], kl0[4], kl1[4];
            LDSM4(kh0, kaddr);
            LDSM4(kh1, kaddr + 32);
            LDSM4(kl0, kaddr + 64);
            LDSM4(kl1, kaddr + 96);

            const int colA = s0 + 16*np + qcol;
            float cA[4], cB[4];
            {
                float2 t0 = *(const float2*)(rel0 + colA);
                float2 t1 = *(const float2*)(rel8 + colA);
                float2 t2 = *(const float2*)(rel0 + colA + 8);
                float2 t3 = *(const float2*)(rel8 + colA + 8);
                cA[0]=t0.x; cA[1]=t0.y; cA[2]=t1.x; cA[3]=t1.y;
                cB[0]=t2.x; cB[1]=t2.y; cB[2]=t3.x; cB[3]=t3.y;
            }
            mma16816(cA, qh0, kh0[0], kh0[1]);
            mma16816(cA, qh1, kh1[0], kh1[1]);
            mma16816(cA, qh0, kl0[0], kl0[1]);
            mma16816(cA, qh1, kl1[0], kl1[1]);
            mma16816(cA, ql0, kh0[0], kh0[1]);
            mma16816(cA, ql1, kh1[0], kh1[1]);

            mma16816(cB, qh0, kh0[2], kh0[3]);
            mma16816(cB, qh1, kh1[2], kh1[3]);
            mma16816(cB, qh0, kl0[2], kl0[3]);
            mma16816(cB, qh1, kl1[2], kl1[3]);
            mma16816(cB, ql0, kh0[2], kh0[3]);
            mma16816(cB, ql1, kh1[2], kh1[3]);

            float pA0 = __expf(cA[0]), pA1 = __expf(cA[1]);
            float pA2 = __expf(cA[2]), pA3 = __expf(cA[3]);
            float pB0 = __expf(cB[0]), pB1 = __expf(cB[1]);
            float pB2 = __expf(cB[2]), pB3 = __expf(cB[3]);
            rsum0 += (pA0 + pA1) + (pB0 + pB1);
            rsum1 += (pA2 + pA3) + (pB2 + pB3);

            uint32_t u0 = packf2(pA0, pA1), u1 = packf2(pA2, pA3);
            uint32_t u2 = packf2(pB0, pB1), u3 = packf2(pB2, pB3);
            aPhi[np][0] = u0; aPhi[np][1] = u1; aPhi[np][2] = u2; aPhi[np][3] = u3;
            aPlo[np][0] = packf2(pA0 - __uint_as_float(u0 << 16),
                                 pA1 - __uint_as_float(u0 & 0xffff0000u));
            aPlo[np][1] = packf2(pA2 - __uint_as_float(u1 << 16),
                                 pA3 - __uint_as_float(u1 & 0xffff0000u));
            aPlo[np][2] = packf2(pB0 - __uint_as_float(u2 << 16),
                                 pB1 - __uint_as_float(u2 & 0xffff0000u));
            aPlo[np][3] = packf2(pB2 - __uint_as_float(u3 << 16),
                                 pB3 - __uint_as_float(u3 & 0xffff0000u));
        }

#pragma unroll
        for (int j = 0; j < 4; j++) {
            uint32_t vaddr = sVb + (16*j + (lane & 15)) * PITCH + (lane >> 4) * 16;
            uint32_t vh0[4], vh1[4], vl0[4], vl1[4];
            LDSM4T(vh0, vaddr);
            LDSM4T(vh1, vaddr + 32);
            LDSM4T(vl0, vaddr + 64);
            LDSM4T(vl1, vaddr + 96);

            mma16816(O[0], aPhi[j], vh0[0], vh0[1]);
            mma16816(O[0], aPhi[j], vl0[0], vl0[1]);
            mma16816(O[0], aPlo[j], vh0[0], vh0[1]);

            mma16816(O[1], aPhi[j], vh0[2], vh0[3]);
            mma16816(O[1], aPhi[j], vl0[2], vl0[3]);
            mma16816(O[1], aPlo[j], vh0[2], vh0[3]);

            mma16816(O[2], aPhi[j], vh1[0], vh1[1]);
            mma16816(O[2], aPhi[j], vl1[0], vl1[1]);
            mma16816(O[2], aPlo[j], vh1[0], vh1[1]);

            mma16816(O[3], aPhi[j], vh1[2], vh1[3]);
            mma16816(O[3], aPhi[j], vl1[2], vl1[3]);
            mma16816(O[3], aPlo[j], vh1[2], vh1[3]);
        }
    }

    // epilogue: normalize + bf16 split into g_ao (row = l*4+n, 1KB [hi|lo])
    rsum0 += __shfl_xor_sync(0xffffffffu, rsum0, 1);
    rsum0 += __shfl_xor_sync(0xffffffffu, rsum0, 2);
    rsum1 += __shfl_xor_sync(0xffffffffu, rsum1, 1);
    rsum1 += __shfl_xor_sync(0xffffffffu, rsum1, 2);
    const float inv0 = 1.0f / rsum0, inv1 = 1.0f / rsum1;

    const int n = bh >> 3, h = bh & 7;
    const int r = l0 + WROW + qrow;
    uint8_t* rp0 = g_ao + ((size_t)r * N_B + n) * 1024;
    uint8_t* rp8 = rp0 + (size_t)8 * N_B * 1024;
#pragma unroll
    for (int t = 0; t < 4; t++) {
        const int e = h * HD_N + t * 8 + qcol;
        uint32_t ha,la,hb,lb;
        split1(O[t][0] * inv0, ha, la); split1(O[t][1] * inv0, hb, lb);
        *(uint32_t*)(rp0 + 2*e)       = ha | (hb << 16);
        *(uint32_t*)(rp0 + 512 + 2*e) = la | (lb << 16);
        split1(O[t][2] * inv1, ha, la); split1(O[t][3] * inv1, hb, lb);
        *(uint32_t*)(rp8 + 2*e)       = ha | (hb << 16);
        *(uint32_t*)(rp8 + 512 + 2*e) = la | (lb << 16);
    }
}

// ---------------------------------------------------------------------------
extern "C" void kernel_launch(void* const* d_in, const int* in_sizes, int n_in,
                              void* d_out, int out_size)
{
    const float* query = (const float*)d_in[0];
    const float* key   = (const float*)d_in[1];
    const float* value = (const float*)d_in[2];
    const float* rel   = (const float*)d_in[3];
    const float* ipw   = (const float*)d_in[4];
    const float* ipb   = (const float*)d_in[5];
    const float* opw   = (const float*)d_in[6];
    const float* opb   = (const float*)d_in[7];
    float* out = (float*)d_out;

    convert_in_kernel<<<dim3(2048, 3), 256>>>(query, key, value);
    convert_w_kernel<<<dim3(64, 4), 256>>>(ipw, opw);

    proj_mma_kernel<<<dim3(128, 2, 3), 128>>>(ipb, out, 0);   // QKV

    attn_mma_kernel<<<dim3(32, 32), 128>>>(rel);

    proj_mma_kernel<<<dim3(128, 2, 1), 128>>>(opb, out, 1);   // out projection
}